// round 7
// baseline (speedup 1.0000x reference)
#include <cuda_runtime.h>

// Problem constants
#define B_ 2
#define T_ 2048
#define C_ 1024
#define H_ 16
#define D_ 64

// Scratch (device globals — no runtime allocation allowed)
__device__ float g_q[B_ * H_ * T_ * D_];   // [B,H,T,D]
__device__ float g_k[B_ * H_ * T_ * D_];
__device__ float g_v[B_ * H_ * T_ * D_];
__device__ float g_y[B_ * T_ * C_];        // [B,T,C] attention output

// ---------------------------------------------------------------------------
// SGEMM mainloop: 128x128 tile, BK=8, 256 threads, 8x8 per thread.
// Double-buffered smem: one __syncthreads per K-step, LDG issued before the
// FFMA block so global latency overlaps compute. As/Bs are [2][8][128].
// Hazard audit: iteration kt reads buf (kt&1), writes buf ((kt+1)&1); the
// barrier at the end of iteration kt-1 guarantees all reads of ((kt+1)&1)
// (done in kt-1) completed before kt's STS touches it.
// ---------------------------------------------------------------------------
__device__ __forceinline__ void sgemm_main(
    const float* __restrict__ A, const float* __restrict__ Bw,
    int K, int N, int bm, int bn,
    float (*acc)[2][4][4], float* __restrict__ As, float* __restrict__ Bs)
{
    int tid  = threadIdx.x;
    int tx   = tid & 15, ty = tid >> 4;
    int arow = tid >> 1, acol = (tid & 1) * 4;
    int brow = tid >> 5, bcol = (tid & 31) * 4;

    const float* Ap = A + (size_t)(bm + arow) * K + acol;
    const float* Bp = Bw + (size_t)brow * N + bn + bcol;

    // Preload tile 0 into buffer 0
    {
        float4 av = *(const float4*)Ap;
        float4 bv = *(const float4*)Bp;
        As[(acol + 0) * 128 + arow] = av.x;
        As[(acol + 1) * 128 + arow] = av.y;
        As[(acol + 2) * 128 + arow] = av.z;
        As[(acol + 3) * 128 + arow] = av.w;
        *(float4*)&Bs[brow * 128 + bcol] = bv;
    }
    __syncthreads();

    int nk = K >> 3;
    for (int kt = 0; kt < nk; kt++) {
        const float* Ac = As + (kt & 1) * 1024;
        const float* Bc = Bs + (kt & 1) * 1024;

        // Issue next tile's global loads early (latency hidden by FFMAs below)
        float4 av, bv;
        bool more = (kt + 1 < nk);
        if (more) {
            Ap += 8;
            Bp += (size_t)8 * N;
            av = *(const float4*)Ap;
            bv = *(const float4*)Bp;
        }

#pragma unroll
        for (int kk = 0; kk < 8; kk++) {
            float4 a0 = *(const float4*)&Ac[kk * 128 + ty * 4];
            float4 a1 = *(const float4*)&Ac[kk * 128 + 64 + ty * 4];
            float4 b0 = *(const float4*)&Bc[kk * 128 + tx * 4];
            float4 b1 = *(const float4*)&Bc[kk * 128 + 64 + tx * 4];
            float ar[2][4] = {{a0.x, a0.y, a0.z, a0.w}, {a1.x, a1.y, a1.z, a1.w}};
            float br[2][4] = {{b0.x, b0.y, b0.z, b0.w}, {b1.x, b1.y, b1.z, b1.w}};
#pragma unroll
            for (int rh = 0; rh < 2; rh++)
#pragma unroll
                for (int ch = 0; ch < 2; ch++)
#pragma unroll
                    for (int i = 0; i < 4; i++)
#pragma unroll
                        for (int j = 0; j < 4; j++)
                            acc[rh][ch][i][j] += ar[rh][i] * br[ch][j];
        }

        if (more) {
            float* An = As + ((kt + 1) & 1) * 1024;
            float* Bn = Bs + ((kt + 1) & 1) * 1024;
            An[(acol + 0) * 128 + arow] = av.x;
            An[(acol + 1) * 128 + arow] = av.y;
            An[(acol + 2) * 128 + arow] = av.z;
            An[(acol + 3) * 128 + arow] = av.w;
            *(float4*)&Bn[brow * 128 + bcol] = bv;
            __syncthreads();
        }
    }
}

// ---------------------------------------------------------------------------
// Kernel 1: qkv = x @ w_attn + b_attn, scattered to g_q/g_k/g_v [B,H,T,D]
// ---------------------------------------------------------------------------
__global__ __launch_bounds__(256) void gemm_qkv_kernel(
    const float* __restrict__ x, const float* __restrict__ w,
    const float* __restrict__ bias)
{
    __shared__ float As[2 * 8 * 128];
    __shared__ float Bs[2 * 8 * 128];
    float acc[2][2][4][4];
#pragma unroll
    for (int a = 0; a < 2; a++)
#pragma unroll
        for (int b = 0; b < 2; b++)
#pragma unroll
            for (int i = 0; i < 4; i++)
#pragma unroll
                for (int j = 0; j < 4; j++) acc[a][b][i][j] = 0.f;

    int bm = blockIdx.y * 128, bn = blockIdx.x * 128;
    sgemm_main(x, w, 1024, 3072, bm, bn, acc, As, Bs);

    int tx = threadIdx.x & 15, ty = threadIdx.x >> 4;
#pragma unroll
    for (int rh = 0; rh < 2; rh++)
#pragma unroll
        for (int i = 0; i < 4; i++) {
            int m  = bm + rh * 64 + ty * 4 + i;
            int bb = m >> 11;          // / T_
            int t  = m & (T_ - 1);
#pragma unroll
            for (int ch = 0; ch < 2; ch++) {
                int n     = bn + ch * 64 + tx * 4;   // 4 consecutive cols, same head
                int which = n >> 10;
                int r     = n & 1023;
                int hh    = r >> 6;
                int dd    = r & 63;
                float4 bi = *(const float4*)&bias[n];
                float4 v  = make_float4(acc[rh][ch][i][0] + bi.x,
                                        acc[rh][ch][i][1] + bi.y,
                                        acc[rh][ch][i][2] + bi.z,
                                        acc[rh][ch][i][3] + bi.w);
                float* dst = (which == 0) ? g_q : (which == 1) ? g_k : g_v;
                *(float4*)&dst[(((bb * H_ + hh) * T_ + t) * D_) + dd] = v;
            }
        }
}

// ---------------------------------------------------------------------------
// Kernel 2: fused causal flash attention, fp32, 64x64 tiles.
//  - Qs [d][m], Ks [d][n], Vs [n][d], Ps [m][PADP] (separate buffer)
//  - half-warp shuffle reductions (row owners = one half-warp)
//  - next-tile K/V prefetched into registers before the P@V loop
//  - 3 __syncthreads per KV tile
//  - LPT scheduling: qt = 31 - blockIdx.x so longest CTAs dispatch first
// ---------------------------------------------------------------------------
#define PADP 68
#define FLASH_SMEM_FLOATS (4096 + 4096 + 4096 + 64 * PADP)
#define FLASH_SMEM_BYTES  (FLASH_SMEM_FLOATS * 4)

__global__ __launch_bounds__(256) void flash_kernel()
{
    extern __shared__ float sm[];
    float* Qs = sm;                       // [d][m] 64x64
    float* Ks = sm + 4096;                // [d][n] 64x64
    float* Vs = sm + 8192;                // [n][d] 64x64
    float* Ps = sm + 12288;               // [m][PADP]

    int tid = threadIdx.x;
    int tx  = tid & 15, ty = tid >> 4;
    int qt  = (int)(gridDim.x - 1u - blockIdx.x);   // longest-tile-first (LPT)
    int h   = blockIdx.y, b = blockIdx.z;
    int q0  = qt * 64;

    const float* Qg = g_q + (size_t)((b * H_ + h) * T_) * D_;
    const float* Kg = g_k + (size_t)((b * H_ + h) * T_) * D_;
    const float* Vg = g_v + (size_t)((b * H_ + h) * T_) * D_;

    // Load Q tile transposed with 1/sqrt(D) folded in: Qs[d][m]
    {
        const float scale = 0.125f;
        int m  = tid & 63;
        int c4 = (tid >> 6) << 2;
#pragma unroll
        for (int it = 0; it < 4; it++) {
            float4 v = *(const float4*)&Qg[(q0 + m) * 64 + c4];
            Qs[(c4 + 0) * 64 + m] = v.x * scale;
            Qs[(c4 + 1) * 64 + m] = v.y * scale;
            Qs[(c4 + 2) * 64 + m] = v.z * scale;
            Qs[(c4 + 3) * 64 + m] = v.w * scale;
            c4 += 16;   // tid+256 advances (i>>6) by 4 -> c4 by 16
        }
    }

    // Prefetch KV tile 0 into registers
    int kn  = tid & 63;            // K: column index n
    int kc4 = (tid >> 6) << 2;     // K: starting d (advances by 16 per chunk)
    int vn  = tid >> 4;            // V: row n (advances by 16 per chunk)
    int vc4 = (tid & 15) << 2;     // V: d offset
    float4 kreg[4], vreg[4];
#pragma unroll
    for (int it = 0; it < 4; it++) {
        kreg[it] = *(const float4*)&Kg[kn * 64 + kc4 + it * 16];
        vreg[it] = *(const float4*)&Vg[(vn + it * 16) * 64 + vc4];
    }

    float mst[4], lst[4], o[4][4];
#pragma unroll
    for (int i = 0; i < 4; i++) {
        mst[i] = -1e30f; lst[i] = 0.f;
#pragma unroll
        for (int j = 0; j < 4; j++) o[i][j] = 0.f;
    }

    for (int tn = 0; tn <= qt; tn++) {
        // Store prefetched K (transposed) and V tiles to smem
#pragma unroll
        for (int it = 0; it < 4; it++) {
            Ks[(kc4 + it * 16 + 0) * 64 + kn] = kreg[it].x;
            Ks[(kc4 + it * 16 + 1) * 64 + kn] = kreg[it].y;
            Ks[(kc4 + it * 16 + 2) * 64 + kn] = kreg[it].z;
            Ks[(kc4 + it * 16 + 3) * 64 + kn] = kreg[it].w;
            *(float4*)&Vs[(vn + it * 16) * 64 + vc4] = vreg[it];
        }
        __syncthreads();   // sync_load: K/V (and Q on iter 0) visible

        // S = Q K^T (scale pre-folded into Q)
        float s[4][4];
#pragma unroll
        for (int i = 0; i < 4; i++)
#pragma unroll
            for (int j = 0; j < 4; j++) s[i][j] = 0.f;

#pragma unroll 8
        for (int d = 0; d < 64; d++) {
            float4 a  = *(const float4*)&Qs[d * 64 + ty * 4];
            float4 bk = *(const float4*)&Ks[d * 64 + tx * 4];
            float ar[4] = {a.x, a.y, a.z, a.w};
            float br[4] = {bk.x, bk.y, bk.z, bk.w};
#pragma unroll
            for (int i = 0; i < 4; i++)
#pragma unroll
                for (int j = 0; j < 4; j++) s[i][j] += ar[i] * br[j];
        }

        // causal mask on diagonal tile
        if (tn == qt) {
#pragma unroll
            for (int i = 0; i < 4; i++)
#pragma unroll
                for (int j = 0; j < 4; j++)
                    if (tx * 4 + j > ty * 4 + i) s[i][j] = -1e30f;
        }

        // online softmax: half-warp shuffle reductions (row = half-warp)
        float alpha[4];
#pragma unroll
        for (int i = 0; i < 4; i++) {
            float v = fmaxf(fmaxf(s[i][0], s[i][1]), fmaxf(s[i][2], s[i][3]));
            v = fmaxf(v, __shfl_xor_sync(0xffffffffu, v, 1));
            v = fmaxf(v, __shfl_xor_sync(0xffffffffu, v, 2));
            v = fmaxf(v, __shfl_xor_sync(0xffffffffu, v, 4));
            v = fmaxf(v, __shfl_xor_sync(0xffffffffu, v, 8));
            float mnew = fmaxf(mst[i], v);
            alpha[i]   = __expf(mst[i] - mnew);
            mst[i]     = mnew;

            float p0 = __expf(s[i][0] - mnew);
            float p1 = __expf(s[i][1] - mnew);
            float p2 = __expf(s[i][2] - mnew);
            float p3 = __expf(s[i][3] - mnew);
            s[i][0] = p0; s[i][1] = p1; s[i][2] = p2; s[i][3] = p3;

            float ls = p0 + p1 + p2 + p3;
            ls += __shfl_xor_sync(0xffffffffu, ls, 1);
            ls += __shfl_xor_sync(0xffffffffu, ls, 2);
            ls += __shfl_xor_sync(0xffffffffu, ls, 4);
            ls += __shfl_xor_sync(0xffffffffu, ls, 8);
            lst[i] = lst[i] * alpha[i] + ls;

            // store this thread's P block row (float4; PADP*4=272B row stride,
            // 272 = 17*16 so every row stays 16B-aligned)
            *(float4*)&Ps[(ty * 4 + i) * PADP + tx * 4] =
                make_float4(p0, p1, p2, p3);
#pragma unroll
            for (int j = 0; j < 4; j++) o[i][j] *= alpha[i];
        }
        __syncthreads();   // sync_p: P visible

        // Prefetch next KV tile (latency hidden behind P@V below)
        if (tn < qt) {
            const float* Kn = Kg + (size_t)(tn + 1) * 64 * 64;
            const float* Vn = Vg + (size_t)(tn + 1) * 64 * 64;
#pragma unroll
            for (int it = 0; it < 4; it++) {
                kreg[it] = *(const float4*)&Kn[kn * 64 + kc4 + it * 16];
                vreg[it] = *(const float4*)&Vn[(vn + it * 16) * 64 + vc4];
            }
        }

        // O += P @ V
#pragma unroll 8
        for (int n = 0; n < 64; n++) {
            float p0 = Ps[(ty * 4 + 0) * PADP + n];
            float p1 = Ps[(ty * 4 + 1) * PADP + n];
            float p2 = Ps[(ty * 4 + 2) * PADP + n];
            float p3 = Ps[(ty * 4 + 3) * PADP + n];
            float4 v4 = *(const float4*)&Vs[n * 64 + tx * 4];
            float vr[4] = {v4.x, v4.y, v4.z, v4.w};
#pragma unroll
            for (int j = 0; j < 4; j++) {
                o[0][j] += p0 * vr[j];
                o[1][j] += p1 * vr[j];
                o[2][j] += p2 * vr[j];
                o[3][j] += p3 * vr[j];
            }
        }
        __syncthreads();   // sync_end: all reads of Ks/Vs/Ps done
    }

    // epilogue: normalize + write to g_y [B,T,C]
#pragma unroll
    for (int i = 0; i < 4; i++) {
        float inv = 1.0f / lst[i];
        int t = q0 + ty * 4 + i;
        float4 v = make_float4(o[i][0] * inv, o[i][1] * inv,
                               o[i][2] * inv, o[i][3] * inv);
        *(float4*)&g_y[((size_t)(b * T_ + t) * C_) + h * D_ + tx * 4] = v;
    }
}

// ---------------------------------------------------------------------------
// Kernel 3: out = y @ w_proj + b_proj
// ---------------------------------------------------------------------------
__global__ __launch_bounds__(256) void gemm_proj_kernel(
    const float* __restrict__ w, const float* __restrict__ bias,
    float* __restrict__ out)
{
    __shared__ float As[2 * 8 * 128];
    __shared__ float Bs[2 * 8 * 128];
    float acc[2][2][4][4];
#pragma unroll
    for (int a = 0; a < 2; a++)
#pragma unroll
        for (int b = 0; b < 2; b++)
#pragma unroll
            for (int i = 0; i < 4; i++)
#pragma unroll
                for (int j = 0; j < 4; j++) acc[a][b][i][j] = 0.f;

    int bm = blockIdx.y * 128, bn = blockIdx.x * 128;
    sgemm_main(g_y, w, 1024, 1024, bm, bn, acc, As, Bs);

    int tx = threadIdx.x & 15, ty = threadIdx.x >> 4;
#pragma unroll
    for (int rh = 0; rh < 2; rh++)
#pragma unroll
        for (int i = 0; i < 4; i++) {
            int m = bm + rh * 64 + ty * 4 + i;
#pragma unroll
            for (int ch = 0; ch < 2; ch++) {
                int n = bn + ch * 64 + tx * 4;
                float4 bi = *(const float4*)&bias[n];
                float4 v  = make_float4(acc[rh][ch][i][0] + bi.x,
                                        acc[rh][ch][i][1] + bi.y,
                                        acc[rh][ch][i][2] + bi.z,
                                        acc[rh][ch][i][3] + bi.w);
                *(float4*)&out[(size_t)m * 1024 + n] = v;
            }
        }
}

// ---------------------------------------------------------------------------
extern "C" void kernel_launch(void* const* d_in, const int* in_sizes, int n_in,
                              void* d_out, int out_size)
{
    const float* x      = (const float*)d_in[0];
    const float* w_attn = (const float*)d_in[1];
    const float* b_attn = (const float*)d_in[2];
    const float* w_proj = (const float*)d_in[3];
    const float* b_proj = (const float*)d_in[4];
    float* out = (float*)d_out;

    cudaFuncSetAttribute(flash_kernel,
                         cudaFuncAttributeMaxDynamicSharedMemorySize,
                         FLASH_SMEM_BYTES);

    gemm_qkv_kernel<<<dim3(24, 32), 256>>>(x, w_attn, b_attn);
    flash_kernel<<<dim3(32, 16, 2), 256, FLASH_SMEM_BYTES>>>();
    gemm_proj_kernel<<<dim3(8, 32), 256>>>(w_proj, b_proj, out);
}

// round 11
// speedup vs baseline: 1.3113x; 1.3113x over previous
#include <cuda_runtime.h>

// Problem constants
#define B_ 2
#define T_ 2048
#define C_ 1024
#define H_ 16
#define D_ 64

// Scratch (device globals — no runtime allocation allowed)
__device__ float g_q[B_ * H_ * T_ * D_];   // [B,H,T,D]
__device__ float g_k[B_ * H_ * T_ * D_];
__device__ float g_v[B_ * H_ * T_ * D_];
__device__ float g_y[B_ * T_ * C_];        // [B,T,C] attention output

// ===========================================================================
// tf32 tensor-core GEMM: 128x128 block tile, BK=16, 256 threads (8 warps),
// warp tile 64x32 (warps 2x4), mma.sync.m16n8k8 tf32.
// smem holds PRE-CONVERTED tf32 bits; layout [k][m]/[k][n], row stride 136
// (136 mod 32 = 8 -> frag loads bank = 8*(lane&3)+(lane>>2), conflict-free).
// Double-buffered, one __syncthreads per stage, LDG prefetch before compute.
// ===========================================================================
#define ASTR 136
#define GEMM_STAGE (16 * ASTR)

__device__ __forceinline__ unsigned f2tf(float f) {
    unsigned u;
    asm("cvt.rna.tf32.f32 %0, %1;" : "=r"(u) : "f"(f));
    return u;
}

__device__ __forceinline__ void mma_tf32(float* c, const unsigned* a, const unsigned* b) {
    asm volatile(
        "mma.sync.aligned.m16n8k8.row.col.f32.tf32.tf32.f32 "
        "{%0,%1,%2,%3}, {%4,%5,%6,%7}, {%8,%9}, {%0,%1,%2,%3};"
        : "+f"(c[0]), "+f"(c[1]), "+f"(c[2]), "+f"(c[3])
        : "r"(a[0]), "r"(a[1]), "r"(a[2]), "r"(a[3]), "r"(b[0]), "r"(b[1]));
}

// acc: 16 tiles (mt*4+nt), 4 floats each
__device__ __forceinline__ void tf32_gemm_main(
    const float* __restrict__ A, const float* __restrict__ Bw,
    int K, int N, int bm, int bn,
    float (*acc)[4], unsigned* __restrict__ As, unsigned* __restrict__ Bs)
{
    int tid  = threadIdx.x;
    int lane = tid & 31, warp = tid >> 5;
    int wm = (warp >> 2) * 64, wn = (warp & 3) * 32;

    int am  = tid & 127;          // A: m row this thread loads
    int akg = tid >> 7;           // A: k-group selector (0/1)
    int bnn = tid & 127;          // B: n column this thread loads
    int bkg = (tid >> 7) * 8;     // B: k-row base (0/8)

    const float* Aq = A + (size_t)(bm + am) * K;
    const float* Bq = Bw + bn + bnn;

    // ---- preload stage 0 ----
    {
        float4 av0 = *(const float4*)(Aq + akg * 4);         // k: akg*4 .. +3
        float4 av1 = *(const float4*)(Aq + (akg + 2) * 4);   // k: akg*4+8 .. +3
        float bv[8];
#pragma unroll
        for (int i = 0; i < 8; i++) bv[i] = Bq[(size_t)(bkg + i) * N];

        unsigned* Ad0 = As + (akg * 4) * ASTR + am;
        Ad0[0 * ASTR] = f2tf(av0.x); Ad0[1 * ASTR] = f2tf(av0.y);
        Ad0[2 * ASTR] = f2tf(av0.z); Ad0[3 * ASTR] = f2tf(av0.w);
        unsigned* Ad1 = As + ((akg + 2) * 4) * ASTR + am;
        Ad1[0 * ASTR] = f2tf(av1.x); Ad1[1 * ASTR] = f2tf(av1.y);
        Ad1[2 * ASTR] = f2tf(av1.z); Ad1[3 * ASTR] = f2tf(av1.w);
        unsigned* Bd = Bs + bkg * ASTR + bnn;
#pragma unroll
        for (int i = 0; i < 8; i++) Bd[i * ASTR] = f2tf(bv[i]);
    }
    __syncthreads();

    int nk = K >> 4;
    for (int kt = 0; kt < nk; kt++) {
        const unsigned* Ac = As + (kt & 1) * GEMM_STAGE;
        const unsigned* Bc = Bs + (kt & 1) * GEMM_STAGE;

        // prefetch next stage's globals (latency hidden by MMAs below)
        float4 av0, av1; float bv[8];
        bool more = (kt + 1 < nk);
        if (more) {
            const float* Ap = Aq + (kt + 1) * 16;
            av0 = *(const float4*)(Ap + akg * 4);
            av1 = *(const float4*)(Ap + (akg + 2) * 4);
            const float* Bp = Bq + (size_t)(kt + 1) * 16 * N;
#pragma unroll
            for (int i = 0; i < 8; i++) bv[i] = Bp[(size_t)(bkg + i) * N];
        }

        int row = lane >> 2, kq = lane & 3;
#pragma unroll
        for (int ks = 0; ks < 16; ks += 8) {
            unsigned a[4][4], b[4][2];
            const unsigned* A0 = Ac + (ks + kq) * ASTR + wm + row;
            const unsigned* A4 = Ac + (ks + 4 + kq) * ASTR + wm + row;
#pragma unroll
            for (int mt = 0; mt < 4; mt++) {
                a[mt][0] = A0[mt * 16];
                a[mt][1] = A0[mt * 16 + 8];
                a[mt][2] = A4[mt * 16];
                a[mt][3] = A4[mt * 16 + 8];
            }
            const unsigned* B0 = Bc + (ks + kq) * ASTR + wn + row;
            const unsigned* B4 = Bc + (ks + 4 + kq) * ASTR + wn + row;
#pragma unroll
            for (int nt = 0; nt < 4; nt++) {
                b[nt][0] = B0[nt * 8];
                b[nt][1] = B4[nt * 8];
            }
#pragma unroll
            for (int mt = 0; mt < 4; mt++)
#pragma unroll
                for (int nt = 0; nt < 4; nt++)
                    mma_tf32(acc[mt * 4 + nt], a[mt], b[nt]);
        }

        if (more) {
            unsigned* An0 = As + ((kt + 1) & 1) * GEMM_STAGE + (akg * 4) * ASTR + am;
            An0[0 * ASTR] = f2tf(av0.x); An0[1 * ASTR] = f2tf(av0.y);
            An0[2 * ASTR] = f2tf(av0.z); An0[3 * ASTR] = f2tf(av0.w);
            unsigned* An1 = As + ((kt + 1) & 1) * GEMM_STAGE + ((akg + 2) * 4) * ASTR + am;
            An1[0 * ASTR] = f2tf(av1.x); An1[1 * ASTR] = f2tf(av1.y);
            An1[2 * ASTR] = f2tf(av1.z); An1[3 * ASTR] = f2tf(av1.w);
            unsigned* Bd = Bs + ((kt + 1) & 1) * GEMM_STAGE + bkg * ASTR + bnn;
#pragma unroll
            for (int i = 0; i < 8; i++) Bd[i * ASTR] = f2tf(bv[i]);
            __syncthreads();
        }
    }
}

// ---------------------------------------------------------------------------
// Kernel 1: qkv = x @ w_attn + b_attn, scattered to g_q/g_k/g_v [B,H,T,D]
// ---------------------------------------------------------------------------
__global__ __launch_bounds__(256, 2) void gemm_qkv_kernel(
    const float* __restrict__ x, const float* __restrict__ w,
    const float* __restrict__ bias)
{
    __shared__ unsigned As[2 * GEMM_STAGE];
    __shared__ unsigned Bs[2 * GEMM_STAGE];
    float acc[16][4];
#pragma unroll
    for (int i = 0; i < 16; i++)
#pragma unroll
        for (int j = 0; j < 4; j++) acc[i][j] = 0.f;

    int bm = blockIdx.y * 128, bn = blockIdx.x * 128;
    tf32_gemm_main(x, w, 1024, 3072, bm, bn, acc, As, Bs);

    int lane = threadIdx.x & 31, warp = threadIdx.x >> 5;
    int wm = (warp >> 2) * 64, wn = (warp & 3) * 32;
#pragma unroll
    for (int mt = 0; mt < 4; mt++) {
        int m0 = bm + wm + mt * 16 + (lane >> 2);
#pragma unroll
        for (int nt = 0; nt < 4; nt++) {
            const float* c = acc[mt * 4 + nt];
            int n0 = bn + wn + nt * 8 + 2 * (lane & 3);
            float2 bi = *(const float2*)&bias[n0];
            int which = n0 >> 10;
            int r     = n0 & 1023;
            int hh    = r >> 6;
            int dd    = r & 63;
            float* dst = (which == 0) ? g_q : (which == 1) ? g_k : g_v;
#pragma unroll
            for (int hrow = 0; hrow < 2; hrow++) {
                int m  = m0 + hrow * 8;
                int bb = m >> 11;
                int t  = m & (T_ - 1);
                float2 v = make_float2(c[hrow * 2 + 0] + bi.x,
                                       c[hrow * 2 + 1] + bi.y);
                *(float2*)&dst[(((bb * H_ + hh) * T_ + t) * D_) + dd] = v;
            }
        }
    }
}

// ---------------------------------------------------------------------------
// Kernel 2: fused causal flash attention, fp32, 64x64 tiles. (unchanged)
// ---------------------------------------------------------------------------
#define PADP 68
#define FLASH_SMEM_FLOATS (4096 + 4096 + 4096 + 64 * PADP)
#define FLASH_SMEM_BYTES  (FLASH_SMEM_FLOATS * 4)

__global__ __launch_bounds__(256) void flash_kernel()
{
    extern __shared__ float sm[];
    float* Qs = sm;                       // [d][m] 64x64
    float* Ks = sm + 4096;                // [d][n] 64x64
    float* Vs = sm + 8192;                // [n][d] 64x64
    float* Ps = sm + 12288;               // [m][PADP]

    int tid = threadIdx.x;
    int tx  = tid & 15, ty = tid >> 4;
    int qt  = (int)(gridDim.x - 1u - blockIdx.x);   // longest-tile-first (LPT)
    int h   = blockIdx.y, b = blockIdx.z;
    int q0  = qt * 64;

    const float* Qg = g_q + (size_t)((b * H_ + h) * T_) * D_;
    const float* Kg = g_k + (size_t)((b * H_ + h) * T_) * D_;
    const float* Vg = g_v + (size_t)((b * H_ + h) * T_) * D_;

    // Load Q tile transposed with 1/sqrt(D) folded in: Qs[d][m]
    {
        const float scale = 0.125f;
        int m  = tid & 63;
        int c4 = (tid >> 6) << 2;
#pragma unroll
        for (int it = 0; it < 4; it++) {
            float4 v = *(const float4*)&Qg[(q0 + m) * 64 + c4];
            Qs[(c4 + 0) * 64 + m] = v.x * scale;
            Qs[(c4 + 1) * 64 + m] = v.y * scale;
            Qs[(c4 + 2) * 64 + m] = v.z * scale;
            Qs[(c4 + 3) * 64 + m] = v.w * scale;
            c4 += 16;
        }
    }

    // Prefetch KV tile 0 into registers
    int kn  = tid & 63;
    int kc4 = (tid >> 6) << 2;
    int vn  = tid >> 4;
    int vc4 = (tid & 15) << 2;
    float4 kreg[4], vreg[4];
#pragma unroll
    for (int it = 0; it < 4; it++) {
        kreg[it] = *(const float4*)&Kg[kn * 64 + kc4 + it * 16];
        vreg[it] = *(const float4*)&Vg[(vn + it * 16) * 64 + vc4];
    }

    float mst[4], lst[4], o[4][4];
#pragma unroll
    for (int i = 0; i < 4; i++) {
        mst[i] = -1e30f; lst[i] = 0.f;
#pragma unroll
        for (int j = 0; j < 4; j++) o[i][j] = 0.f;
    }

    for (int tn = 0; tn <= qt; tn++) {
#pragma unroll
        for (int it = 0; it < 4; it++) {
            Ks[(kc4 + it * 16 + 0) * 64 + kn] = kreg[it].x;
            Ks[(kc4 + it * 16 + 1) * 64 + kn] = kreg[it].y;
            Ks[(kc4 + it * 16 + 2) * 64 + kn] = kreg[it].z;
            Ks[(kc4 + it * 16 + 3) * 64 + kn] = kreg[it].w;
            *(float4*)&Vs[(vn + it * 16) * 64 + vc4] = vreg[it];
        }
        __syncthreads();   // sync_load

        float s[4][4];
#pragma unroll
        for (int i = 0; i < 4; i++)
#pragma unroll
            for (int j = 0; j < 4; j++) s[i][j] = 0.f;

#pragma unroll 8
        for (int d = 0; d < 64; d++) {
            float4 a  = *(const float4*)&Qs[d * 64 + ty * 4];
            float4 bk = *(const float4*)&Ks[d * 64 + tx * 4];
            float ar[4] = {a.x, a.y, a.z, a.w};
            float br[4] = {bk.x, bk.y, bk.z, bk.w};
#pragma unroll
            for (int i = 0; i < 4; i++)
#pragma unroll
                for (int j = 0; j < 4; j++) s[i][j] += ar[i] * br[j];
        }

        if (tn == qt) {
#pragma unroll
            for (int i = 0; i < 4; i++)
#pragma unroll
                for (int j = 0; j < 4; j++)
                    if (tx * 4 + j > ty * 4 + i) s[i][j] = -1e30f;
        }

        float alpha[4];
#pragma unroll
        for (int i = 0; i < 4; i++) {
            float v = fmaxf(fmaxf(s[i][0], s[i][1]), fmaxf(s[i][2], s[i][3]));
            v = fmaxf(v, __shfl_xor_sync(0xffffffffu, v, 1));
            v = fmaxf(v, __shfl_xor_sync(0xffffffffu, v, 2));
            v = fmaxf(v, __shfl_xor_sync(0xffffffffu, v, 4));
            v = fmaxf(v, __shfl_xor_sync(0xffffffffu, v, 8));
            float mnew = fmaxf(mst[i], v);
            alpha[i]   = __expf(mst[i] - mnew);
            mst[i]     = mnew;

            float p0 = __expf(s[i][0] - mnew);
            float p1 = __expf(s[i][1] - mnew);
            float p2 = __expf(s[i][2] - mnew);
            float p3 = __expf(s[i][3] - mnew);
            s[i][0] = p0; s[i][1] = p1; s[i][2] = p2; s[i][3] = p3;

            float ls = p0 + p1 + p2 + p3;
            ls += __shfl_xor_sync(0xffffffffu, ls, 1);
            ls += __shfl_xor_sync(0xffffffffu, ls, 2);
            ls += __shfl_xor_sync(0xffffffffu, ls, 4);
            ls += __shfl_xor_sync(0xffffffffu, ls, 8);
            lst[i] = lst[i] * alpha[i] + ls;

            *(float4*)&Ps[(ty * 4 + i) * PADP + tx * 4] =
                make_float4(p0, p1, p2, p3);
#pragma unroll
            for (int j = 0; j < 4; j++) o[i][j] *= alpha[i];
        }
        __syncthreads();   // sync_p

        if (tn < qt) {
            const float* Kn = Kg + (size_t)(tn + 1) * 64 * 64;
            const float* Vn = Vg + (size_t)(tn + 1) * 64 * 64;
#pragma unroll
            for (int it = 0; it < 4; it++) {
                kreg[it] = *(const float4*)&Kn[kn * 64 + kc4 + it * 16];
                vreg[it] = *(const float4*)&Vn[(vn + it * 16) * 64 + vc4];
            }
        }

#pragma unroll 8
        for (int n = 0; n < 64; n++) {
            float p0 = Ps[(ty * 4 + 0) * PADP + n];
            float p1 = Ps[(ty * 4 + 1) * PADP + n];
            float p2 = Ps[(ty * 4 + 2) * PADP + n];
            float p3 = Ps[(ty * 4 + 3) * PADP + n];
            float4 v4 = *(const float4*)&Vs[n * 64 + tx * 4];
            float vr[4] = {v4.x, v4.y, v4.z, v4.w};
#pragma unroll
            for (int j = 0; j < 4; j++) {
                o[0][j] += p0 * vr[j];
                o[1][j] += p1 * vr[j];
                o[2][j] += p2 * vr[j];
                o[3][j] += p3 * vr[j];
            }
        }
        __syncthreads();   // sync_end
    }

#pragma unroll
    for (int i = 0; i < 4; i++) {
        float inv = 1.0f / lst[i];
        int t = q0 + ty * 4 + i;
        float4 v = make_float4(o[i][0] * inv, o[i][1] * inv,
                               o[i][2] * inv, o[i][3] * inv);
        *(float4*)&g_y[((size_t)(b * T_ + t) * C_) + h * D_ + tx * 4] = v;
    }
}

// ---------------------------------------------------------------------------
// Kernel 3: out = y @ w_proj + b_proj  (tf32 tensor cores)
// ---------------------------------------------------------------------------
__global__ __launch_bounds__(256, 2) void gemm_proj_kernel(
    const float* __restrict__ w, const float* __restrict__ bias,
    float* __restrict__ out)
{
    __shared__ unsigned As[2 * GEMM_STAGE];
    __shared__ unsigned Bs[2 * GEMM_STAGE];
    float acc[16][4];
#pragma unroll
    for (int i = 0; i < 16; i++)
#pragma unroll
        for (int j = 0; j < 4; j++) acc[i][j] = 0.f;

    int bm = blockIdx.y * 128, bn = blockIdx.x * 128;
    tf32_gemm_main(g_y, w, 1024, 1024, bm, bn, acc, As, Bs);

    int lane = threadIdx.x & 31, warp = threadIdx.x >> 5;
    int wm = (warp >> 2) * 64, wn = (warp & 3) * 32;
#pragma unroll
    for (int mt = 0; mt < 4; mt++) {
        int m0 = bm + wm + mt * 16 + (lane >> 2);
#pragma unroll
        for (int nt = 0; nt < 4; nt++) {
            const float* c = acc[mt * 4 + nt];
            int n0 = bn + wn + nt * 8 + 2 * (lane & 3);
            float2 bi = *(const float2*)&bias[n0];
            *(float2*)&out[(size_t)m0 * 1024 + n0] =
                make_float2(c[0] + bi.x, c[1] + bi.y);
            *(float2*)&out[(size_t)(m0 + 8) * 1024 + n0] =
                make_float2(c[2] + bi.x, c[3] + bi.y);
        }
    }
}

// ---------------------------------------------------------------------------
extern "C" void kernel_launch(void* const* d_in, const int* in_sizes, int n_in,
                              void* d_out, int out_size)
{
    const float* x      = (const float*)d_in[0];
    const float* w_attn = (const float*)d_in[1];
    const float* b_attn = (const float*)d_in[2];
    const float* w_proj = (const float*)d_in[3];
    const float* b_proj = (const float*)d_in[4];
    float* out = (float*)d_out;

    cudaFuncSetAttribute(flash_kernel,
                         cudaFuncAttributeMaxDynamicSharedMemorySize,
                         FLASH_SMEM_BYTES);

    gemm_qkv_kernel<<<dim3(24, 32), 256>>>(x, w_attn, b_attn);
    flash_kernel<<<dim3(32, 16, 2), 256, FLASH_SMEM_BYTES>>>();
    gemm_proj_kernel<<<dim3(8, 32), 256>>>(w_proj, b_proj, out);
}